// round 1
// baseline (speedup 1.0000x reference)
#include <cuda_runtime.h>
#include <math.h>
#include <float.h>

#define NROWS 16384
#define DIM   64
#define NK    8192
#define TOPK  10
#define TC    256
#define NTILES (NK / TC)
#define RPB   16

// ---- global scratch (no allocs allowed) ----
__device__ float g_counts[NK];
__device__ float g_loss;
__device__ float g_nvalid;

// out layout: quantized [0,1048576), total_loss @1048576, idx @1048577+row,
// min_d @1064961+row, perplexity @1081345
#define LOSS_OFF 1048576
#define IDX_OFF  1048577
#define MD_OFF   1064961
#define PERP_OFF 1081345

__global__ void vq_zero() {
    int t = blockIdx.x * blockDim.x + threadIdx.x;
    if (t < NK) g_counts[t] = 0.f;
    if (t == 0) { g_loss = 0.f; g_nvalid = 0.f; }
}

__device__ __forceinline__ bool lessdi(float a, int ai, float b, int bi) {
    return (a < b) || (a == b && ai < bi);
}

// branch-free sorted insert; static indexing only (keeps arrays in registers)
__device__ __forceinline__ void topk_insert(float dist, int ci,
                                            float (&td)[TOPK], int (&ti)[TOPK]) {
    if (lessdi(dist, ci, td[TOPK-1], ti[TOPK-1])) {
        #pragma unroll
        for (int s = TOPK-1; s >= 1; --s) {
            bool cm1 = lessdi(dist, ci, td[s-1], ti[s-1]);
            bool cs  = lessdi(dist, ci, td[s],   ti[s]);
            float nv = cm1 ? td[s-1] : dist;
            int  nvi = cm1 ? ti[s-1] : ci;
            if (cs) { td[s] = nv; ti[s] = nvi; }
        }
        if (lessdi(dist, ci, td[0], ti[0])) { td[0] = dist; ti[0] = ci; }
    }
}

__device__ __forceinline__ void finish_row(
    float (&td)[TOPK], int (&ti)[TOPK],
    int lrow, int grow, int lane,
    const float* __restrict__ cb, const float* __restrict__ gum,
    float* __restrict__ out, const float* x_s, const float* nx_s,
    float* md, int* mi)
{
    const unsigned FULL = 0xffffffffu;
    // merge 32 sorted per-lane lists -> global top-10 (ascending by (dist, idx))
    #pragma unroll
    for (int r = 0; r < TOPK; ++r) {
        float cd = td[0]; int ci = ti[0];
        #pragma unroll
        for (int off = 16; off > 0; off >>= 1) {
            float od = __shfl_xor_sync(FULL, cd, off);
            int   oi = __shfl_xor_sync(FULL, ci, off);
            if (lessdi(od, oi, cd, ci)) { cd = od; ci = oi; }
        }
        unsigned m = __ballot_sync(FULL, td[0] == cd && ti[0] == ci);
        int winner = __ffs(m) - 1;
        if (lane == winner) {
            #pragma unroll
            for (int s = 0; s < TOPK-1; ++s) { td[s] = td[s+1]; ti[s] = ti[s+1]; }
            td[TOPK-1] = FLT_MAX; ti[TOPK-1] = 0x7fffffff;
        }
        if (lane == 0) { md[r] = cd; mi[r] = ci; }
    }
    __syncwarp();
    // gumbel-max sampling over the 10 candidates (first max on tie, like argmax)
    float y = -FLT_MAX; int jj = lane;
    if (lane < TOPK) y = -md[lane] + gum[(size_t)grow * TOPK + lane];
    #pragma unroll
    for (int off = 16; off > 0; off >>= 1) {
        float oy = __shfl_xor_sync(FULL, y,  off);
        int   oj = __shfl_xor_sync(FULL, jj, off);
        if (oy > y || (oy == y && oj < jj)) { y = oy; jj = oj; }
    }
    int   idx  = mi[jj];
    float mind = md[jj];

    float nx = nx_s[lrow];
    bool valid = nx > 1e-12f;              // norm > 1e-6
    float vm = valid ? 1.f : 0.f;

    float2 cv = ((const float2*)(cb + (size_t)idx * DIM))[lane];
    float2 xv = ((const float2*)(x_s + lrow * DIM))[lane];
    ((float2*)(out + (size_t)grow * DIM))[lane] = make_float2(cv.x * vm, cv.y * vm);

    float lp = vm * ((cv.x - xv.x) * (cv.x - xv.x) + (cv.y - xv.y) * (cv.y - xv.y));
    #pragma unroll
    for (int off = 16; off > 0; off >>= 1) lp += __shfl_xor_sync(FULL, lp, off);

    if (lane == 0) {
        atomicAdd(&g_loss, lp);
        atomicAdd(&g_counts[idx], vm);
        atomicAdd(&g_nvalid, vm);
        out[IDX_OFF + grow] = valid ? (float)idx : 0.f;
        out[MD_OFF  + grow] = valid ? mind : 0.f;
    }
}

__global__ void __launch_bounds__(256, 2)
vq_main(const float* __restrict__ inp, const float* __restrict__ cb,
        const float* __restrict__ gum, float* __restrict__ out)
{
    extern __shared__ float smem[];
    float* x_s  = smem;                   // RPB*DIM = 1024
    float* nx_s = x_s + RPB * DIM;        // 16
    float* e_s  = nx_s + 16;              // 64*256 = 16384 (dim-major, swizzled)
    float* ne_s = e_s + DIM * 256;        // 256
    float* md_s = ne_s + 256;             // 8*TOPK
    int*   mi_s = (int*)(md_s + 8 * TOPK);// 8*TOPK

    const int t    = threadIdx.x;
    const int lane = t & 31;
    const int w    = t >> 5;
    const int row0 = blockIdx.x * RPB;

    // load 16 input rows
    ((float4*)x_s)[t] = ((const float4*)(inp + (size_t)row0 * DIM))[t];
    __syncthreads();
    if (t < RPB) {
        float s = 0.f;
        #pragma unroll
        for (int d = 0; d < DIM; ++d) { float v = x_s[t * DIM + d]; s = fmaf(v, v, s); }
        nx_s[t] = s;
    }
    __syncthreads();

    const int lr0 = w * 2, lr1 = w * 2 + 1;
    const float nx0 = nx_s[lr0], nx1 = nx_s[lr1];

    float td0[TOPK], td1[TOPK]; int ti0[TOPK], ti1[TOPK];
    #pragma unroll
    for (int i = 0; i < TOPK; ++i) {
        td0[i] = FLT_MAX; td1[i] = FLT_MAX; ti0[i] = 0x7fffffff; ti1[i] = 0x7fffffff;
    }

    for (int tile = 0; tile < NTILES; ++tile) {
        __syncthreads();   // prev epilogue done reading ne_s before overwrite
        // coalesced load of 256 codes x 64 dims, transpose to dim-major with XOR swizzle:
        //   element (d,c) at e_s[d*256 + ((((c>>2) ^ ((d>>2)&15)) << 2) | (c&3))]
        const float4* cb4 = (const float4*)(cb + (size_t)(tile * TC) * DIM);
        #pragma unroll
        for (int i = 0; i < 16; ++i) {
            int j = t + (i << 8);
            float4 v = cb4[j];
            int c  = j >> 4;
            int d4 = j & 15;
            int base = (d4 << 2) * 256 + ((((c >> 2) ^ d4) << 2) | (c & 3));
            e_s[base]       = v.x;
            e_s[base + 256] = v.y;
            e_s[base + 512] = v.z;
            e_s[base + 768] = v.w;
        }
        __syncthreads();
        // ||e||^2 for code t
        {
            float s = 0.f;
            int chi = t >> 2, clo = t & 3;
            #pragma unroll
            for (int d = 0; d < DIM; ++d) {
                float v = e_s[d * 256 + (((chi ^ (d >> 2)) << 2) | clo)];
                s = fmaf(v, v, s);
            }
            ne_s[t] = s;
        }
        // GEMM: 2 rows x 8 codes per lane
        float a0[8], a1[8];
        #pragma unroll
        for (int i = 0; i < 8; ++i) { a0[i] = 0.f; a1[i] = 0.f; }
        #pragma unroll 4
        for (int d4 = 0; d4 < 16; ++d4) {
            int ca = (lane ^ d4) << 2;
            #pragma unroll
            for (int k = 0; k < 4; ++k) {
                int d = (d4 << 2) + k;
                float4 ea = *(const float4*)(e_s + d * 256 + ca);
                float4 eb = *(const float4*)(e_s + d * 256 + ca + 128);
                float xa = x_s[lr0 * DIM + d];
                float xb = x_s[lr1 * DIM + d];
                a0[0] = fmaf(xa, ea.x, a0[0]); a0[1] = fmaf(xa, ea.y, a0[1]);
                a0[2] = fmaf(xa, ea.z, a0[2]); a0[3] = fmaf(xa, ea.w, a0[3]);
                a0[4] = fmaf(xa, eb.x, a0[4]); a0[5] = fmaf(xa, eb.y, a0[5]);
                a0[6] = fmaf(xa, eb.z, a0[6]); a0[7] = fmaf(xa, eb.w, a0[7]);
                a1[0] = fmaf(xb, ea.x, a1[0]); a1[1] = fmaf(xb, ea.y, a1[1]);
                a1[2] = fmaf(xb, ea.z, a1[2]); a1[3] = fmaf(xb, ea.w, a1[3]);
                a1[4] = fmaf(xb, eb.x, a1[4]); a1[5] = fmaf(xb, eb.y, a1[5]);
                a1[6] = fmaf(xb, eb.z, a1[6]); a1[7] = fmaf(xb, eb.w, a1[7]);
            }
        }
        __syncthreads();  // all ne_s writes visible
        // distances + top-k update
        int cbase = (tile << 8) + (lane << 2);
        #pragma unroll
        for (int k = 0; k < 4; ++k) {
            float neA = ne_s[(lane << 2) + k];
            float neB = ne_s[(lane << 2) + k + 128];
            int ciA = cbase + k, ciB = cbase + k + 128;
            topk_insert(nx0 + neA - 2.f * a0[k],     ciA, td0, ti0);
            topk_insert(nx0 + neB - 2.f * a0[4 + k], ciB, td0, ti0);
            topk_insert(nx1 + neA - 2.f * a1[k],     ciA, td1, ti1);
            topk_insert(nx1 + neB - 2.f * a1[4 + k], ciB, td1, ti1);
        }
    }

    finish_row(td0, ti0, lr0, row0 + lr0, lane, cb, gum, out, x_s, nx_s,
               md_s + w * TOPK, mi_s + w * TOPK);
    finish_row(td1, ti1, lr1, row0 + lr1, lane, cb, gum, out, x_s, nx_s,
               md_s + w * TOPK, mi_s + w * TOPK);
}

__global__ void vq_finalize(float* __restrict__ out) {
    __shared__ float red[256];
    int t = threadIdx.x;
    float nv = fmaxf(g_nvalid, 1.f);
    float h = 0.f;
    for (int i = t; i < NK; i += 256) {
        float p = g_counts[i] / nv;
        h += p * logf(p + 1e-10f);
    }
    red[t] = h; __syncthreads();
    for (int s = 128; s > 0; s >>= 1) { if (t < s) red[t] += red[t + s]; __syncthreads(); }
    if (t == 0) {
        float H = red[0];
        float perp = expf(-H);
        float ploss = -logf(perp + 1e-10f);
        float lvq = g_loss / (nv * (float)DIM);
        out[LOSS_OFF] = lvq + 0.01f * ploss;
        out[PERP_OFF] = perp;
    }
}

extern "C" void kernel_launch(void* const* d_in, const int* in_sizes, int n_in,
                              void* d_out, int out_size) {
    const float* inp = (const float*)d_in[0];
    const float* cbp = (const float*)d_in[1];
    const float* gum = (const float*)d_in[2];
    float* out = (float*)d_out;
    int smem_bytes = (RPB * DIM + 16 + DIM * 256 + 256 + 8 * TOPK) * 4 + 8 * TOPK * 4;
    cudaFuncSetAttribute((const void*)vq_main,
                         cudaFuncAttributeMaxDynamicSharedMemorySize, smem_bytes);
    vq_zero<<<(NK + 255) / 256, 256>>>();
    vq_main<<<NROWS / RPB, 256, smem_bytes>>>(inp, cbp, gum, out);
    vq_finalize<<<1, 256>>>(out);
}